// round 11
// baseline (speedup 1.0000x reference)
#include <cuda_runtime.h>
#include <cstdint>

#define DD 1024
#define RR 4096
#define BB 32
#define NEG_INF_F (-1e9f)

// Scratch (no device allocation allowed anywhere)
__device__ float g_projv[BB * DD];
__device__ float g_scores[BB * RR];
// U pre-rounded to tf32 bit patterns, re-laid-out as [koct][n][8]:
// element (k, n) lives at ((k>>3)*1024 + n)*8 + (k&3)*2 + ((k>>2)&1)
__device__ float g_Ur2[DD * DD];

// ---------------------------------------------------------------------------
// helpers
// ---------------------------------------------------------------------------
__device__ __forceinline__ uint32_t f2tf(float x) {
    uint32_t r;
    asm("cvt.rna.tf32.f32 %0, %1;" : "=r"(r) : "f"(x));
    return r;
}

__device__ __forceinline__ float fast_tanh(float x) {
    float e = __expf(2.0f * x);
    return 1.0f - __fdividef(2.0f, e + 1.0f);
}

__device__ __forceinline__ void mma_tf32(float c[4], const uint32_t a[4], const uint32_t b[2]) {
    asm volatile(
        "mma.sync.aligned.m16n8k8.row.col.f32.tf32.tf32.f32 "
        "{%0,%1,%2,%3}, {%4,%5,%6,%7}, {%8,%9}, {%0,%1,%2,%3};\n"
        : "+f"(c[0]), "+f"(c[1]), "+f"(c[2]), "+f"(c[3])
        : "r"(a[0]), "r"(a[1]), "r"(a[2]), "r"(a[3]), "r"(b[0]), "r"(b[1]));
}

__device__ __forceinline__ void cp_async16(uint32_t sdst, const void* gsrc) {
    asm volatile("cp.async.cg.shared.global [%0], [%1], 16;\n" :: "r"(sdst), "l"(gsrc));
}

// ldmatrix x4: four 8x8 b16 tiles == one m16k8 tf32 A fragment (raw fp32 bits)
__device__ __forceinline__ void ldsm_x4(uint32_t r[4], uint32_t saddr) {
    asm volatile("ldmatrix.sync.aligned.m8n8.x4.shared.b16 {%0,%1,%2,%3}, [%4];\n"
                 : "=r"(r[0]), "=r"(r[1]), "=r"(r[2]), "=r"(r[3]) : "r"(saddr));
}

// ---------------------------------------------------------------------------
// Kernel 0: round U to tf32 and re-layout to [koct][n][8] (idx=(k&3)*2+(k>>2&1))
// grid (4, 128): n = bx*256+tx, koct = by
// ---------------------------------------------------------------------------
__global__ void roundU_kernel(const float* __restrict__ U) {
    const int n = blockIdx.x * 256 + threadIdx.x;
    const int koct = blockIdx.y;
    float o[8];
#pragma unroll
    for (int idx = 0; idx < 8; ++idx) {
        const int k = koct * 8 + ((idx & 1) << 2) + (idx >> 1);
        o[idx] = __uint_as_float(f2tf(U[(size_t)k * DD + n]));
    }
    float4* dst = (float4*)(g_Ur2 + ((size_t)koct * DD + n) * 8);
    dst[0] = make_float4(o[0], o[1], o[2], o[3]);
    dst[1] = make_float4(o[4], o[5], o[6], o[7]);
}

// ---------------------------------------------------------------------------
// Kernel 1: proj_v = vector @ W  (B x D) fp32.
// grid (16 n-tiles, 4 batch-groups), block 256 = 64 n x 4 k-quarters.
// Each block holds 8 batch vectors (transposed, pad-9) in smem and reads its
// W column panel ONCE -> total W traffic 16MB (was 128MB).
// ---------------------------------------------------------------------------
__global__ void projv_kernel(const float* __restrict__ vec, const float* __restrict__ W) {
    __shared__ float vst[DD * 9];        // vst[k*9 + bl], bl = batch-in-group
    __shared__ float part[4][64][8];     // [kp][n_l][bl]
    const int t = threadIdx.x;
    const int n0 = blockIdx.x * 64;
    const int bg = blockIdx.y;           // batch group: b = bg*8 + bl
    const int n_l = t & 63;
    const int kp = t >> 6;

    // load 8 batch vectors (coalesced) into transposed smem
#pragma unroll
    for (int i = 0; i < 32; ++i) {
        const int f = t + i * 256;       // f < 8192
        const int bl = f >> 10;
        const int k = f & 1023;
        vst[k * 9 + bl] = vec[(size_t)(bg * 8 + bl) * DD + k];
    }
    __syncthreads();

    float acc[8];
#pragma unroll
    for (int bl = 0; bl < 8; ++bl) acc[bl] = 0.0f;

    const float* Wp = W + (size_t)(kp * 256) * DD + n0 + n_l;
    const float* vp = vst + (kp * 256) * 9;
#pragma unroll 4
    for (int k = 0; k < 256; ++k) {
        const float w = Wp[(size_t)k * DD];
#pragma unroll
        for (int bl = 0; bl < 8; ++bl)
            acc[bl] = fmaf(w, vp[k * 9 + bl], acc[bl]);
    }
#pragma unroll
    for (int bl = 0; bl < 8; ++bl) part[kp][n_l][bl] = acc[bl];
    __syncthreads();

    // reduce over kp: 512 outputs, 2 per thread
#pragma unroll
    for (int i = 0; i < 2; ++i) {
        const int idx = t + i * 256;     // idx < 512
        const int bl = idx >> 6;
        const int nn = idx & 63;
        g_projv[(size_t)(bg * 8 + bl) * DD + n0 + nn] =
            part[0][nn][bl] + part[1][nn][bl] + part[2][nn][bl] + part[3][nn][bl];
    }
}

// ---------------------------------------------------------------------------
// Kernel 2: fused proj_m GEMM (legacy tf32 mma.sync) + tanh(+proj_v).v
// CTA 128(M) x 256(N-pass, x4), K-chunk 32, FOUR smem slots,
// TWO chunks per barrier: wait -> sync -> issue(s+2,s+3) -> compute(s,s+1)
// as one continuous 8-ks double-buffered fragment pipeline.
// 256 threads, 8 warps (2M x 4N), warp tile 64x64. A frags via ldmatrix.x4.
// Stage: A 128x32 XOR-swizzled (16KB) + B [4 koct][256 n][8] (32KB) = 48KB.
// 4 stages + 128 score floats = 197120 B.  (unchanged from R10 — proven)
// ---------------------------------------------------------------------------
#define STG_F  12288
#define B_OFF  4096
#define NTOT   128           // 4 N-passes x 32 k-chunks

__global__ __launch_bounds__(256, 1)
void fused_gemm_legacy(const float* __restrict__ matrix, const float* __restrict__ vvec) {
    extern __shared__ __align__(128) float smem[];
    float* s_score = smem + 4 * STG_F;

    const int tid = threadIdx.x;
    const int warp = tid >> 5;
    const int lane = tid & 31;
    const int wm = warp & 1;       // 0..1  (64 rows each)
    const int wn = warp >> 1;      // 0..3  (64 cols each)
    const int g = lane >> 2;       // 0..7
    const int t = lane & 3;        // 0..3

    const int b = blockIdx.y;
    const int row0 = blockIdx.x * 128;

    if (tid < 128) s_score[tid] = 0.0f;

    const float* Ag = matrix + ((size_t)b * RR + row0) * DD;
    const uint32_t sb = (uint32_t)__cvta_generic_to_shared(smem);

    // ldmatrix lane roles: mat = lane>>3, r7 = lane&7
    const int r7 = lane & 7;
    const int mh = lane >> 4;                 // mat>>1: +4 fp32 cols
    const int mrow = ((lane >> 3) & 1) * 8 + r7;  // (mat&1)*8 + row-in-mat

    // A cp.async mapping: rows ar+32i, 16B chunk ac
    const int ar = tid >> 3, ac = tid & 7;
    const uint32_t a_sw = (uint32_t)(ar & 7);  // row&7 invariant under +32

    auto issue_loads = [&](int sl) {
        const uint32_t slot = (uint32_t)(sl & 3);
        const int kt = sl & 31;
        const int n0 = (sl >> 5) * 256;
        const uint32_t abase = sb + slot * (STG_F * 4u);
        const uint32_t bbase = abase + B_OFF * 4u;
        const float* asrc = Ag + (size_t)ar * DD + kt * 32 + ac * 4;
#pragma unroll
        for (int i = 0; i < 4; ++i) {
            const int row = ar + i * 32;
            cp_async16(abase + (uint32_t)(row * 128) + ((((uint32_t)ac) ^ a_sw) << 4),
                       asrc + (size_t)i * 32 * DD);
        }
        // B: 2048 16B-chunks; chunk c: koct_l=c>>9, n=(c>>1)&255, half=c&1
#pragma unroll
        for (int i = 0; i < 8; ++i) {
            const int c = i * 256 + tid;
            const int koct_l = c >> 9;
            const int n = (c >> 1) & 255;
            const int half = c & 1;
            cp_async16(bbase + (uint32_t)c * 16u,
                       g_Ur2 + (((size_t)(kt * 4 + koct_l) * DD + n0 + n) << 3) + half * 4);
        }
    };

    // prefetch chunks 0,1 into slots 0,1 (single group)
    issue_loads(0);
    issue_loads(1);
    asm volatile("cp.async.commit_group;\n");

    float acc[4][8][4];
#pragma unroll
    for (int i = 0; i < 4; ++i)
#pragma unroll
        for (int j = 0; j < 8; ++j)
#pragma unroll
            for (int q = 0; q < 4; ++q) acc[i][j][q] = 0.0f;

    const float* pv = g_projv + b * DD;

    for (int s = 0; s < NTOT; s += 2) {
        asm volatile("cp.async.wait_group 0;\n");
        __syncthreads();

        // issue next pair (slots a+2, a+3; readers use a, a+1 -> disjoint)
        if (s + 2 < NTOT) {
            issue_loads(s + 2);
            issue_loads(s + 3);
            asm volatile("cp.async.commit_group;\n");
        }

        // compute chunks s (slot a) and s+1 (slot a+1) as one 8-step pipeline
        const uint32_t sl0 = (uint32_t)(s & 3);
        const uint32_t sl1 = (uint32_t)((s + 1) & 3);
        const uint32_t Ab32c[2] = { sb + sl0 * (STG_F * 4u), sb + sl1 * (STG_F * 4u) };
        const float* Bbc[2] = { smem + sl0 * STG_F + B_OFF, smem + sl1 * STG_F + B_OFF };

        uint32_t afr[2][4][4];
        uint32_t bfr[2][8][2];
        auto load_frags = [&](int kk, int buf) {
            const int c = kk >> 2;
            const int ks = kk & 3;
            const uint32_t cx = (uint32_t)((2 * ks + mh) ^ r7) << 4;
#pragma unroll
            for (int i = 0; i < 4; ++i) {
                const int row = wm * 64 + i * 16 + mrow;
                ldsm_x4(afr[buf][i], Ab32c[c] + (uint32_t)(row * 128) + cx);
            }
            const float* bks = Bbc[c] + ks * 2048 + 2 * t;
#pragma unroll
            for (int j = 0; j < 8; ++j) {
                const float2 p = *(const float2*)(bks + (wn * 64 + j * 8 + g) * 8);
                bfr[buf][j][0] = __float_as_uint(p.x);   // k = t
                bfr[buf][j][1] = __float_as_uint(p.y);   // k = t+4
            }
        };

        load_frags(0, 0);
#pragma unroll
        for (int kk = 0; kk < 8; ++kk) {
            const int cur = kk & 1;
            if (kk < 7) load_frags(kk + 1, cur ^ 1);
#pragma unroll
            for (int i = 0; i < 4; ++i)
#pragma unroll
                for (int j = 0; j < 8; ++j)
                    mma_tf32(acc[i][j], afr[cur][i], bfr[cur][j]);
        }

        if (((s + 1) & 31) == 31) {
            // epilogue for this 256-col pass: tanh(acc + pv) . v
            const int n0 = (s >> 5) * 256;
            float ps[4][2];
#pragma unroll
            for (int i = 0; i < 4; ++i) { ps[i][0] = 0.0f; ps[i][1] = 0.0f; }
#pragma unroll
            for (int j = 0; j < 8; ++j) {
                const int cb = n0 + wn * 64 + j * 8 + 2 * t;
                const float2 pvv = *(const float2*)(pv + cb);
                const float2 vv = *(const float2*)(vvec + cb);
#pragma unroll
                for (int i = 0; i < 4; ++i) {
                    ps[i][0] += fast_tanh(acc[i][j][0] + pvv.x) * vv.x
                              + fast_tanh(acc[i][j][1] + pvv.y) * vv.y;
                    ps[i][1] += fast_tanh(acc[i][j][2] + pvv.x) * vv.x
                              + fast_tanh(acc[i][j][3] + pvv.y) * vv.y;
                    acc[i][j][0] = 0.0f; acc[i][j][1] = 0.0f;
                    acc[i][j][2] = 0.0f; acc[i][j][3] = 0.0f;
                }
            }
#pragma unroll
            for (int i = 0; i < 4; ++i)
#pragma unroll
                for (int h = 0; h < 2; ++h) {
                    float x = ps[i][h];
                    x += __shfl_xor_sync(0xffffffffu, x, 1);
                    x += __shfl_xor_sync(0xffffffffu, x, 2);
                    if (t == 0) atomicAdd(&s_score[wm * 64 + i * 16 + h * 8 + g], x);
                }
        }
    }

    __syncthreads();
    if (tid < 128) g_scores[(size_t)b * RR + row0 + tid] = s_score[tid];
}

// ---------------------------------------------------------------------------
// Kernel 3: masked softmax over R per batch. grid (B), 256 threads.
// ---------------------------------------------------------------------------
__global__ void softmax_kernel(const int* __restrict__ mask, float* __restrict__ out) {
    const int b = blockIdx.x;
    __shared__ float red[256];
    const float* s = g_scores + (size_t)b * RR;
    const int* m = mask + (size_t)b * RR;

    float l[16];
    float lmax = -3.0e38f;
#pragma unroll
    for (int i = 0; i < 16; ++i) {
        const int r = threadIdx.x + i * 256;
        l[i] = (m[r] > 0) ? s[r] : NEG_INF_F;
        lmax = fmaxf(lmax, l[i]);
    }
    red[threadIdx.x] = lmax;
    __syncthreads();
    for (int off = 128; off > 0; off >>= 1) {
        if (threadIdx.x < off) red[threadIdx.x] = fmaxf(red[threadIdx.x], red[threadIdx.x + off]);
        __syncthreads();
    }
    const float gmax = red[0];
    __syncthreads();

    float e[16];
    float lsum = 0.0f;
#pragma unroll
    for (int i = 0; i < 16; ++i) {
        e[i] = __expf(l[i] - gmax);
        lsum += e[i];
    }
    red[threadIdx.x] = lsum;
    __syncthreads();
    for (int off = 128; off > 0; off >>= 1) {
        if (threadIdx.x < off) red[threadIdx.x] += red[threadIdx.x + off];
        __syncthreads();
    }
    const float inv = __frcp_rn(red[0]);
#pragma unroll
    for (int i = 0; i < 16; ++i)
        out[(size_t)b * RR + threadIdx.x + i * 256] = e[i] * inv;
}

// ---------------------------------------------------------------------------
// launch
// ---------------------------------------------------------------------------
extern "C" void kernel_launch(void* const* d_in, const int* in_sizes, int n_in,
                              void* d_out, int out_size) {
    (void)in_sizes; (void)n_in; (void)out_size;
    const float* vec    = (const float*)d_in[0];  // (32,1024)
    const float* matrix = (const float*)d_in[1];  // (32,4096,1024)
    const int*   mask   = (const int*)  d_in[2];  // (32,4096)
    const float* W      = (const float*)d_in[3];  // (1024,1024)
    const float* U      = (const float*)d_in[4];  // (1024,1024)
    const float* v      = (const float*)d_in[5];  // (1024,1)
    float* out = (float*)d_out;                   // (32,4096)

    const int SMEM = (4 * STG_F + 128) * 4;  // 197120 B
    static int configured = 0;
    if (!configured) {
        cudaFuncSetAttribute(fused_gemm_legacy, cudaFuncAttributeMaxDynamicSharedMemorySize, SMEM);
        configured = 1;
    }

    roundU_kernel<<<dim3(4, 128), 256>>>(U);
    projv_kernel<<<dim3(16, 4), 256>>>(vec, W);
    fused_gemm_legacy<<<dim3(RR / 128, BB), 256, SMEM>>>(matrix, v);
    softmax_kernel<<<BB, 256>>>(mask, out);
}

// round 12
// speedup vs baseline: 1.0498x; 1.0498x over previous
#include <cuda_runtime.h>
#include <cstdint>

#define DD 1024
#define RR 4096
#define BB 32
#define NEG_INF_F (-1e9f)

// Scratch (no device allocation allowed anywhere)
__device__ float g_projv[BB * DD];
__device__ float g_scores[BB * RR];
// U pre-rounded to tf32 bit patterns, re-laid-out as [koct][n][8]:
// element (k, n) lives at ((k>>3)*1024 + n)*8 + (k&3)*2 + ((k>>2)&1)
__device__ float g_Ur2[DD * DD];

// ---------------------------------------------------------------------------
// helpers
// ---------------------------------------------------------------------------
__device__ __forceinline__ uint32_t f2tf(float x) {
    uint32_t r;
    asm("cvt.rna.tf32.f32 %0, %1;" : "=r"(r) : "f"(x));
    return r;
}

// single-MUFU tanh (sm_75+): max abs err ~2^-11, halves epilogue MUFU pressure
__device__ __forceinline__ float fast_tanh(float x) {
    float y;
    asm("tanh.approx.f32 %0, %1;" : "=f"(y) : "f"(x));
    return y;
}

__device__ __forceinline__ void mma_tf32(float c[4], const uint32_t a[4], const uint32_t b[2]) {
    asm volatile(
        "mma.sync.aligned.m16n8k8.row.col.f32.tf32.tf32.f32 "
        "{%0,%1,%2,%3}, {%4,%5,%6,%7}, {%8,%9}, {%0,%1,%2,%3};\n"
        : "+f"(c[0]), "+f"(c[1]), "+f"(c[2]), "+f"(c[3])
        : "r"(a[0]), "r"(a[1]), "r"(a[2]), "r"(a[3]), "r"(b[0]), "r"(b[1]));
}

__device__ __forceinline__ void cp_async16(uint32_t sdst, const void* gsrc) {
    asm volatile("cp.async.cg.shared.global [%0], [%1], 16;\n" :: "r"(sdst), "l"(gsrc));
}

// ldmatrix x4: four 8x8 b16 tiles == one m16k8 tf32 A fragment (raw fp32 bits)
__device__ __forceinline__ void ldsm_x4(uint32_t r[4], uint32_t saddr) {
    asm volatile("ldmatrix.sync.aligned.m8n8.x4.shared.b16 {%0,%1,%2,%3}, [%4];\n"
                 : "=r"(r[0]), "=r"(r[1]), "=r"(r[2]), "=r"(r[3]) : "r"(saddr));
}

// ---------------------------------------------------------------------------
// Kernel 0: round U to tf32 and re-layout to [koct][n][8] (idx=(k&3)*2+(k>>2&1))
// grid (4, 128): n = bx*256+tx, koct = by
// ---------------------------------------------------------------------------
__global__ void roundU_kernel(const float* __restrict__ U) {
    const int n = blockIdx.x * 256 + threadIdx.x;
    const int koct = blockIdx.y;
    float o[8];
#pragma unroll
    for (int idx = 0; idx < 8; ++idx) {
        const int k = koct * 8 + ((idx & 1) << 2) + (idx >> 1);
        o[idx] = __uint_as_float(f2tf(U[(size_t)k * DD + n]));
    }
    float4* dst = (float4*)(g_Ur2 + ((size_t)koct * DD + n) * 8);
    dst[0] = make_float4(o[0], o[1], o[2], o[3]);
    dst[1] = make_float4(o[4], o[5], o[6], o[7]);
}

// ---------------------------------------------------------------------------
// Kernel 1: proj_v = vector @ W  (B x D) fp32, k-split x4 within block
// (R10 version — proven; R11's low-occupancy variant regressed)
// ---------------------------------------------------------------------------
__global__ void projv_kernel(const float* __restrict__ vec, const float* __restrict__ W) {
    __shared__ float vs[DD];
    __shared__ float part[4][64];
    const int b = blockIdx.y;
    const int n0 = blockIdx.x * 64;
    const int n = threadIdx.x & 63;
    const int kp = threadIdx.x >> 6;

    for (int k = threadIdx.x; k < DD; k += 256) vs[k] = vec[b * DD + k];
    __syncthreads();

    const float* Wp = W + (size_t)(kp * 256) * DD + n0 + n;
    const float* vp = vs + kp * 256;
    float acc = 0.0f;
#pragma unroll 8
    for (int k = 0; k < 256; ++k) acc = fmaf(vp[k], Wp[(size_t)k * DD], acc);
    part[kp][n] = acc;
    __syncthreads();
    if (kp == 0)
        g_projv[b * DD + n0 + n] = part[0][n] + part[1][n] + part[2][n] + part[3][n];
}

// ---------------------------------------------------------------------------
// Kernel 2: fused proj_m GEMM (legacy tf32 mma.sync) + tanh(+proj_v).v
// CTA 128(M) x 256(N-pass, x4), K-chunk 32, FOUR smem slots,
// TWO chunks per barrier: wait -> sync -> issue(s+2,s+3) -> compute(s,s+1)
// as one continuous 8-ks double-buffered fragment pipeline.
// 256 threads, 8 warps (2M x 4N), warp tile 64x64. A frags via ldmatrix.x4.
// Stage: A 128x32 XOR-swizzled (16KB) + B [4 koct][256 n][8] (32KB) = 48KB.
// 4 stages + 128 score floats = 197120 B.  (structure unchanged from R10)
// ---------------------------------------------------------------------------
#define STG_F  12288
#define B_OFF  4096
#define NTOT   128           // 4 N-passes x 32 k-chunks

__global__ __launch_bounds__(256, 1)
void fused_gemm_legacy(const float* __restrict__ matrix, const float* __restrict__ vvec) {
    extern __shared__ __align__(128) float smem[];
    float* s_score = smem + 4 * STG_F;

    const int tid = threadIdx.x;
    const int warp = tid >> 5;
    const int lane = tid & 31;
    const int wm = warp & 1;       // 0..1  (64 rows each)
    const int wn = warp >> 1;      // 0..3  (64 cols each)
    const int g = lane >> 2;       // 0..7
    const int t = lane & 3;        // 0..3

    const int b = blockIdx.y;
    const int row0 = blockIdx.x * 128;

    if (tid < 128) s_score[tid] = 0.0f;

    const float* Ag = matrix + ((size_t)b * RR + row0) * DD;
    const uint32_t sb = (uint32_t)__cvta_generic_to_shared(smem);

    // ldmatrix lane roles: mat = lane>>3, r7 = lane&7
    const int r7 = lane & 7;
    const int mh = lane >> 4;                 // mat>>1: +4 fp32 cols
    const int mrow = ((lane >> 3) & 1) * 8 + r7;  // (mat&1)*8 + row-in-mat

    // A cp.async mapping: rows ar+32i, 16B chunk ac
    const int ar = tid >> 3, ac = tid & 7;
    const uint32_t a_sw = (uint32_t)(ar & 7);  // row&7 invariant under +32

    auto issue_loads = [&](int sl) {
        const uint32_t slot = (uint32_t)(sl & 3);
        const int kt = sl & 31;
        const int n0 = (sl >> 5) * 256;
        const uint32_t abase = sb + slot * (STG_F * 4u);
        const uint32_t bbase = abase + B_OFF * 4u;
        const float* asrc = Ag + (size_t)ar * DD + kt * 32 + ac * 4;
#pragma unroll
        for (int i = 0; i < 4; ++i) {
            const int row = ar + i * 32;
            cp_async16(abase + (uint32_t)(row * 128) + ((((uint32_t)ac) ^ a_sw) << 4),
                       asrc + (size_t)i * 32 * DD);
        }
        // B: 2048 16B-chunks; chunk c: koct_l=c>>9, n=(c>>1)&255, half=c&1
#pragma unroll
        for (int i = 0; i < 8; ++i) {
            const int c = i * 256 + tid;
            const int koct_l = c >> 9;
            const int n = (c >> 1) & 255;
            const int half = c & 1;
            cp_async16(bbase + (uint32_t)c * 16u,
                       g_Ur2 + (((size_t)(kt * 4 + koct_l) * DD + n0 + n) << 3) + half * 4);
        }
    };

    // prefetch chunks 0,1 into slots 0,1 (single group)
    issue_loads(0);
    issue_loads(1);
    asm volatile("cp.async.commit_group;\n");

    float acc[4][8][4];
#pragma unroll
    for (int i = 0; i < 4; ++i)
#pragma unroll
        for (int j = 0; j < 8; ++j)
#pragma unroll
            for (int q = 0; q < 4; ++q) acc[i][j][q] = 0.0f;

    const float* pv = g_projv + b * DD;

    for (int s = 0; s < NTOT; s += 2) {
        asm volatile("cp.async.wait_group 0;\n");
        __syncthreads();

        // issue next pair (slots a+2, a+3; readers use a, a+1 -> disjoint)
        if (s + 2 < NTOT) {
            issue_loads(s + 2);
            issue_loads(s + 3);
            asm volatile("cp.async.commit_group;\n");
        }

        // compute chunks s (slot a) and s+1 (slot a+1) as one 8-step pipeline
        const uint32_t sl0 = (uint32_t)(s & 3);
        const uint32_t sl1 = (uint32_t)((s + 1) & 3);
        const uint32_t Ab32c[2] = { sb + sl0 * (STG_F * 4u), sb + sl1 * (STG_F * 4u) };
        const float* Bbc[2] = { smem + sl0 * STG_F + B_OFF, smem + sl1 * STG_F + B_OFF };

        uint32_t afr[2][4][4];
        uint32_t bfr[2][8][2];
        auto load_frags = [&](int kk, int buf) {
            const int c = kk >> 2;
            const int ks = kk & 3;
            const uint32_t cx = (uint32_t)((2 * ks + mh) ^ r7) << 4;
#pragma unroll
            for (int i = 0; i < 4; ++i) {
                const int row = wm * 64 + i * 16 + mrow;
                ldsm_x4(afr[buf][i], Ab32c[c] + (uint32_t)(row * 128) + cx);
            }
            const float* bks = Bbc[c] + ks * 2048 + 2 * t;
#pragma unroll
            for (int j = 0; j < 8; ++j) {
                const float2 p = *(const float2*)(bks + (wn * 64 + j * 8 + g) * 8);
                bfr[buf][j][0] = __float_as_uint(p.x);   // k = t
                bfr[buf][j][1] = __float_as_uint(p.y);   // k = t+4
            }
        };

        load_frags(0, 0);
#pragma unroll
        for (int kk = 0; kk < 8; ++kk) {
            const int cur = kk & 1;
            if (kk < 7) load_frags(kk + 1, cur ^ 1);
#pragma unroll
            for (int i = 0; i < 4; ++i)
#pragma unroll
                for (int j = 0; j < 8; ++j)
                    mma_tf32(acc[i][j], afr[cur][i], bfr[cur][j]);
        }

        if (((s + 1) & 31) == 31) {
            // epilogue for this 256-col pass: tanh(acc + pv) . v  (1 MUFU/val)
            const int n0 = (s >> 5) * 256;
            float ps[4][2];
#pragma unroll
            for (int i = 0; i < 4; ++i) { ps[i][0] = 0.0f; ps[i][1] = 0.0f; }
#pragma unroll
            for (int j = 0; j < 8; ++j) {
                const int cb = n0 + wn * 64 + j * 8 + 2 * t;
                const float2 pvv = *(const float2*)(pv + cb);
                const float2 vv = *(const float2*)(vvec + cb);
#pragma unroll
                for (int i = 0; i < 4; ++i) {
                    ps[i][0] = fmaf(fast_tanh(acc[i][j][0] + pvv.x), vv.x, ps[i][0]);
                    ps[i][0] = fmaf(fast_tanh(acc[i][j][1] + pvv.y), vv.y, ps[i][0]);
                    ps[i][1] = fmaf(fast_tanh(acc[i][j][2] + pvv.x), vv.x, ps[i][1]);
                    ps[i][1] = fmaf(fast_tanh(acc[i][j][3] + pvv.y), vv.y, ps[i][1]);
                    acc[i][j][0] = 0.0f; acc[i][j][1] = 0.0f;
                    acc[i][j][2] = 0.0f; acc[i][j][3] = 0.0f;
                }
            }
#pragma unroll
            for (int i = 0; i < 4; ++i)
#pragma unroll
                for (int h = 0; h < 2; ++h) {
                    float x = ps[i][h];
                    x += __shfl_xor_sync(0xffffffffu, x, 1);
                    x += __shfl_xor_sync(0xffffffffu, x, 2);
                    if (t == 0) atomicAdd(&s_score[wm * 64 + i * 16 + h * 8 + g], x);
                }
        }
    }

    __syncthreads();
    if (tid < 128) g_scores[(size_t)b * RR + row0 + tid] = s_score[tid];
}

// ---------------------------------------------------------------------------
// Kernel 3: masked softmax over R per batch. grid (B), 256 threads.
// ---------------------------------------------------------------------------
__global__ void softmax_kernel(const int* __restrict__ mask, float* __restrict__ out) {
    const int b = blockIdx.x;
    __shared__ float red[256];
    const float* s = g_scores + (size_t)b * RR;
    const int* m = mask + (size_t)b * RR;

    float l[16];
    float lmax = -3.0e38f;
#pragma unroll
    for (int i = 0; i < 16; ++i) {
        const int r = threadIdx.x + i * 256;
        l[i] = (m[r] > 0) ? s[r] : NEG_INF_F;
        lmax = fmaxf(lmax, l[i]);
    }
    red[threadIdx.x] = lmax;
    __syncthreads();
    for (int off = 128; off > 0; off >>= 1) {
        if (threadIdx.x < off) red[threadIdx.x] = fmaxf(red[threadIdx.x], red[threadIdx.x + off]);
        __syncthreads();
    }
    const float gmax = red[0];
    __syncthreads();

    float e[16];
    float lsum = 0.0f;
#pragma unroll
    for (int i = 0; i < 16; ++i) {
        e[i] = __expf(l[i] - gmax);
        lsum += e[i];
    }
    red[threadIdx.x] = lsum;
    __syncthreads();
    for (int off = 128; off > 0; off >>= 1) {
        if (threadIdx.x < off) red[threadIdx.x] += red[threadIdx.x + off];
        __syncthreads();
    }
    const float inv = __frcp_rn(red[0]);
#pragma unroll
    for (int i = 0; i < 16; ++i)
        out[(size_t)b * RR + threadIdx.x + i * 256] = e[i] * inv;
}

// ---------------------------------------------------------------------------
// launch
// ---------------------------------------------------------------------------
extern "C" void kernel_launch(void* const* d_in, const int* in_sizes, int n_in,
                              void* d_out, int out_size) {
    (void)in_sizes; (void)n_in; (void)out_size;
    const float* vec    = (const float*)d_in[0];  // (32,1024)
    const float* matrix = (const float*)d_in[1];  // (32,4096,1024)
    const int*   mask   = (const int*)  d_in[2];  // (32,4096)
    const float* W      = (const float*)d_in[3];  // (1024,1024)
    const float* U      = (const float*)d_in[4];  // (1024,1024)
    const float* v      = (const float*)d_in[5];  // (1024,1)
    float* out = (float*)d_out;                   // (32,4096)

    const int SMEM = (4 * STG_F + 128) * 4;  // 197120 B
    static int configured = 0;
    if (!configured) {
        cudaFuncSetAttribute(fused_gemm_legacy, cudaFuncAttributeMaxDynamicSharedMemorySize, SMEM);
        configured = 1;
    }

    roundU_kernel<<<dim3(4, 128), 256>>>(U);
    projv_kernel<<<dim3(DD / 64, BB), 256>>>(vec, W);
    fused_gemm_legacy<<<dim3(RR / 128, BB), 256, SMEM>>>(matrix, v);
    softmax_kernel<<<BB, 256>>>(mask, out);
}

// round 13
// speedup vs baseline: 1.6414x; 1.5635x over previous
#include <cuda_runtime.h>
#include <cuda_fp16.h>
#include <cstdint>

#define DD 1024
#define RR 4096
#define BB 32
#define NEG_INF_F (-1e9f)

// Scratch (no runtime device allocation allowed; static __device__ arrays OK)
__device__ float g_projv[BB * DD];
__device__ float g_scores[BB * RR];
__device__ __half g_Ah[(size_t)BB * RR * DD];   // 256MB: matrix pre-converted to fp16
// U fp16, packed per (k16-group, n): 16 halves in order {0,1,8,9,2,3,10,11,4,5,12,13,6,7,14,15}
// so thread tg reads 8B at offset 4*tg halves -> {b0,b1} of the m16n8k16 B fragment.
__device__ __half g_Uh2[DD * DD];

// ---------------------------------------------------------------------------
// helpers
// ---------------------------------------------------------------------------
__device__ __forceinline__ float fast_tanh(float x) {
    float y;
    asm("tanh.approx.f32 %0, %1;" : "=f"(y) : "f"(x));
    return y;
}

__device__ __forceinline__ void mma_fp16(float c[4], const uint32_t a[4], const uint32_t b[2]) {
    asm volatile(
        "mma.sync.aligned.m16n8k16.row.col.f32.f16.f16.f32 "
        "{%0,%1,%2,%3}, {%4,%5,%6,%7}, {%8,%9}, {%0,%1,%2,%3};\n"
        : "+f"(c[0]), "+f"(c[1]), "+f"(c[2]), "+f"(c[3])
        : "r"(a[0]), "r"(a[1]), "r"(a[2]), "r"(a[3]), "r"(b[0]), "r"(b[1]));
}

__device__ __forceinline__ void cp_async16(uint32_t sdst, const void* gsrc) {
    asm volatile("cp.async.cg.shared.global [%0], [%1], 16;\n" :: "r"(sdst), "l"(gsrc));
}

// ldmatrix x4 (b16): four 8x8 fp16 tiles == one m16n8k16 A fragment
__device__ __forceinline__ void ldsm_x4(uint32_t r[4], uint32_t saddr) {
    asm volatile("ldmatrix.sync.aligned.m8n8.x4.shared.b16 {%0,%1,%2,%3}, [%4];\n"
                 : "=r"(r[0]), "=r"(r[1]), "=r"(r[2]), "=r"(r[3]) : "r"(saddr));
}

// ---------------------------------------------------------------------------
// Kernel 0a: convert matrix fp32 -> fp16 (RN). One float4 per thread.
// grid 131072 x 256 covers 32*4096*1024 elements.
// ---------------------------------------------------------------------------
__global__ void convA_kernel(const float* __restrict__ M) {
    const size_t idx = (size_t)blockIdx.x * 256 + threadIdx.x;  // float4 index
    const float4 v = ((const float4*)M)[idx];
    __half2 h0 = __floats2half2_rn(v.x, v.y);
    __half2 h1 = __floats2half2_rn(v.z, v.w);
    uint2 o;
    o.x = *(uint32_t*)&h0;
    o.y = *(uint32_t*)&h1;
    ((uint2*)g_Ah)[idx] = o;
}

// ---------------------------------------------------------------------------
// Kernel 0b: pack U fp32 -> fp16 [k16-group][n][16] with fragment-order k.
// grid 256 x 256: one thread per (kg, n).
// ---------------------------------------------------------------------------
__global__ void packU_kernel(const float* __restrict__ U) {
    const int id = blockIdx.x * 256 + threadIdx.x;   // 0..65535
    const int kg = id >> 10;
    const int n = id & 1023;
    const int ord[16] = {0, 1, 8, 9, 2, 3, 10, 11, 4, 5, 12, 13, 6, 7, 14, 15};
    __half h[16];
#pragma unroll
    for (int i = 0; i < 16; ++i)
        h[i] = __float2half_rn(U[(size_t)(kg * 16 + ord[i]) * DD + n]);
    uint4* dst = (uint4*)(g_Uh2 + (size_t)id * 16);
    dst[0] = *(uint4*)&h[0];
    dst[1] = *(uint4*)&h[8];
}

// ---------------------------------------------------------------------------
// Kernel 1: proj_v = vector @ W  (B x D) fp32, k-split x4 (R10 version, proven)
// ---------------------------------------------------------------------------
__global__ void projv_kernel(const float* __restrict__ vec, const float* __restrict__ W) {
    __shared__ float vs[DD];
    __shared__ float part[4][64];
    const int b = blockIdx.y;
    const int n0 = blockIdx.x * 64;
    const int n = threadIdx.x & 63;
    const int kp = threadIdx.x >> 6;

    for (int k = threadIdx.x; k < DD; k += 256) vs[k] = vec[b * DD + k];
    __syncthreads();

    const float* Wp = W + (size_t)(kp * 256) * DD + n0 + n;
    const float* vp = vs + kp * 256;
    float acc = 0.0f;
#pragma unroll 8
    for (int k = 0; k < 256; ++k) acc = fmaf(vp[k], Wp[(size_t)k * DD], acc);
    part[kp][n] = acc;
    __syncthreads();
    if (kp == 0)
        g_projv[b * DD + n0 + n] = part[0][n] + part[1][n] + part[2][n] + part[3][n];
}

// ---------------------------------------------------------------------------
// Kernel 2: fused proj_m GEMM (fp16 m16n8k16) + tanh(+proj_v).v
// CTA 128(M) x 256(N-pass, x4), K-chunk 64 (x16), FOUR smem slots,
// TWO chunks per barrier, continuous 8-step double-buffered frag pipeline.
// 256 threads, 8 warps (2M x 4N), warp tile 64x64.
// Stage: A 128x64 fp16 XOR-swizzled (16KB) + B [4 k16][256 n][32B] (32KB) = 48KB.
// 4 stages + 128 score floats = 197120 B. Same skeleton as R10/R12.
// ---------------------------------------------------------------------------
#define STG_B  49152u
#define B_OFFB 16384u
#define NTOT   64            // 4 N-passes x 16 K64-chunks

__global__ __launch_bounds__(256, 1)
void fused_gemm_fp16(const float* __restrict__ vvec) {
    extern __shared__ __align__(128) float smem[];
    float* s_score = (float*)((char*)smem + 4 * STG_B);

    const int tid = threadIdx.x;
    const int warp = tid >> 5;
    const int lane = tid & 31;
    const int wm = warp & 1;       // 0..1  (64 rows each)
    const int wn = warp >> 1;      // 0..3  (64 cols each)
    const int g = lane >> 2;       // 0..7
    const int t = lane & 3;        // 0..3

    const int b = blockIdx.y;
    const int row0 = blockIdx.x * 128;

    if (tid < 128) s_score[tid] = 0.0f;

    const __half* Ag = g_Ah + ((size_t)b * RR + row0) * DD;
    const uint32_t sb = (uint32_t)__cvta_generic_to_shared(smem);

    // ldmatrix lane roles
    const int r7 = lane & 7;
    const int mh = lane >> 4;                      // col 16B-half (k +8)
    const int mrow = ((lane >> 3) & 1) * 8 + r7;   // row-in-16-tile

    // A cp.async mapping: rows ar+32i (i<4), 16B chunk ac (8 halves)
    const int ar = tid >> 3, ac = tid & 7;

    auto issue_loads = [&](int sl) {
        const uint32_t slot = (uint32_t)(sl & 3);
        const int kt = sl & 15;
        const int n0 = (sl >> 4) * 256;
        const uint32_t abase = sb + slot * STG_B;
        const uint32_t bbase = abase + B_OFFB;
        const __half* asrc = Ag + (size_t)ar * DD + kt * 64 + ac * 8;
#pragma unroll
        for (int i = 0; i < 4; ++i) {
            const int row = ar + i * 32;
            cp_async16(abase + (uint32_t)(row * 128) + ((((uint32_t)ac) ^ (uint32_t)(row & 7)) << 4),
                       asrc + (size_t)i * 32 * DD);
        }
        // B: 2048 16B-chunks; chunk c: kg_l=c>>9, n=(c>>1)&255, half=c&1
#pragma unroll
        for (int i = 0; i < 8; ++i) {
            const int c = i * 256 + tid;
            const int kg_l = c >> 9;
            const int n = (c >> 1) & 255;
            const int half = c & 1;
            cp_async16(bbase + (uint32_t)c * 16u,
                       g_Uh2 + ((size_t)(kt * 4 + kg_l) * DD + n0 + n) * 16 + half * 8);
        }
    };

    // prefetch chunks 0,1 into slots 0,1
    issue_loads(0);
    issue_loads(1);
    asm volatile("cp.async.commit_group;\n");

    float acc[4][8][4];
#pragma unroll
    for (int i = 0; i < 4; ++i)
#pragma unroll
        for (int j = 0; j < 8; ++j)
#pragma unroll
            for (int q = 0; q < 4; ++q) acc[i][j][q] = 0.0f;

    const float* pv = g_projv + b * DD;

    for (int s = 0; s < NTOT; s += 2) {
        asm volatile("cp.async.wait_group 0;\n");
        __syncthreads();

        // issue next pair (slots a+2, a+3; readers use a, a+1 -> disjoint)
        if (s + 2 < NTOT) {
            issue_loads(s + 2);
            issue_loads(s + 3);
            asm volatile("cp.async.commit_group;\n");
        }

        const uint32_t sl0 = (uint32_t)(s & 3);
        const uint32_t sl1 = (uint32_t)((s + 1) & 3);
        const uint32_t Ab32c[2] = { sb + sl0 * STG_B, sb + sl1 * STG_B };
        const __half* Bhc[2] = {
            (const __half*)((const char*)smem + sl0 * STG_B + B_OFFB),
            (const __half*)((const char*)smem + sl1 * STG_B + B_OFFB) };

        uint32_t afr[2][4][4];
        uint32_t bfr[2][8][2];
        auto load_frags = [&](int kk, int buf) {
            const int c = kk >> 2;
            const int ks = kk & 3;   // k16-group within the chunk
            const uint32_t cx = (uint32_t)((2 * ks + mh) ^ r7) << 4;
#pragma unroll
            for (int i = 0; i < 4; ++i) {
                const int row = wm * 64 + i * 16 + mrow;
                ldsm_x4(afr[buf][i], Ab32c[c] + (uint32_t)(row * 128) + cx);
            }
            const __half* bks = Bhc[c] + ks * 4096 + t * 4;  // (ks*256 cols)*16
#pragma unroll
            for (int j = 0; j < 8; ++j) {
                const uint2 p = *(const uint2*)(bks + (wn * 64 + j * 8 + g) * 16);
                bfr[buf][j][0] = p.x;   // k = 2t, 2t+1
                bfr[buf][j][1] = p.y;   // k = 2t+8, 2t+9
            }
        };

        load_frags(0, 0);
#pragma unroll
        for (int kk = 0; kk < 8; ++kk) {
            const int cur = kk & 1;
            if (kk < 7) load_frags(kk + 1, cur ^ 1);
#pragma unroll
            for (int i = 0; i < 4; ++i)
#pragma unroll
                for (int j = 0; j < 8; ++j)
                    mma_fp16(acc[i][j], afr[cur][i], bfr[cur][j]);
        }

        if (((s + 1) & 15) == 15) {
            // epilogue for this 256-col pass: tanh(acc + pv) . v
            const int n0 = (s >> 4) * 256;
            float ps[4][2];
#pragma unroll
            for (int i = 0; i < 4; ++i) { ps[i][0] = 0.0f; ps[i][1] = 0.0f; }
#pragma unroll
            for (int j = 0; j < 8; ++j) {
                const int cb = n0 + wn * 64 + j * 8 + 2 * t;
                const float2 pvv = *(const float2*)(pv + cb);
                const float2 vv = *(const float2*)(vvec + cb);
#pragma unroll
                for (int i = 0; i < 4; ++i) {
                    ps[i][0] = fmaf(fast_tanh(acc[i][j][0] + pvv.x), vv.x, ps[i][0]);
                    ps[i][0] = fmaf(fast_tanh(acc[i][j][1] + pvv.y), vv.y, ps[i][0]);
                    ps[i][1] = fmaf(fast_tanh(acc[i][j][2] + pvv.x), vv.x, ps[i][1]);
                    ps[i][1] = fmaf(fast_tanh(acc[i][j][3] + pvv.y), vv.y, ps[i][1]);
                    acc[i][j][0] = 0.0f; acc[i][j][1] = 0.0f;
                    acc[i][j][2] = 0.0f; acc[i][j][3] = 0.0f;
                }
            }
#pragma unroll
            for (int i = 0; i < 4; ++i)
#pragma unroll
                for (int h = 0; h < 2; ++h) {
                    float x = ps[i][h];
                    x += __shfl_xor_sync(0xffffffffu, x, 1);
                    x += __shfl_xor_sync(0xffffffffu, x, 2);
                    if (t == 0) atomicAdd(&s_score[wm * 64 + i * 16 + h * 8 + g], x);
                }
        }
    }

    __syncthreads();
    if (tid < 128) g_scores[(size_t)b * RR + row0 + tid] = s_score[tid];
}

// ---------------------------------------------------------------------------
// Kernel 3: masked softmax over R per batch. grid (B), 256 threads.
// ---------------------------------------------------------------------------
__global__ void softmax_kernel(const int* __restrict__ mask, float* __restrict__ out) {
    const int b = blockIdx.x;
    __shared__ float red[256];
    const float* s = g_scores + (size_t)b * RR;
    const int* m = mask + (size_t)b * RR;

    float l[16];
    float lmax = -3.0e38f;
#pragma unroll
    for (int i = 0; i < 16; ++i) {
        const int r = threadIdx.x + i * 256;
        l[i] = (m[r] > 0) ? s[r] : NEG_INF_F;
        lmax = fmaxf(lmax, l[i]);
    }
    red[threadIdx.x] = lmax;
    __syncthreads();
    for (int off = 128; off > 0; off >>= 1) {
        if (threadIdx.x < off) red[threadIdx.x] = fmaxf(red[threadIdx.x], red[threadIdx.x + off]);
        __syncthreads();
    }
    const float gmax = red[0];
    __syncthreads();

    float e[16];
    float lsum = 0.0f;
#pragma unroll
    for (int i = 0; i < 16; ++i) {
        e[i] = __expf(l[i] - gmax);
        lsum += e[i];
    }
    red[threadIdx.x] = lsum;
    __syncthreads();
    for (int off = 128; off > 0; off >>= 1) {
        if (threadIdx.x < off) red[threadIdx.x] += red[threadIdx.x + off];
        __syncthreads();
    }
    const float inv = __frcp_rn(red[0]);
#pragma unroll
    for (int i = 0; i < 16; ++i)
        out[(size_t)b * RR + threadIdx.x + i * 256] = e[i] * inv;
}

// ---------------------------------------------------------------------------
// launch
// ---------------------------------------------------------------------------
extern "C" void kernel_launch(void* const* d_in, const int* in_sizes, int n_in,
                              void* d_out, int out_size) {
    (void)in_sizes; (void)n_in; (void)out_size;
    const float* vec    = (const float*)d_in[0];  // (32,1024)
    const float* matrix = (const float*)d_in[1];  // (32,4096,1024)
    const int*   mask   = (const int*)  d_in[2];  // (32,4096)
    const float* W      = (const float*)d_in[3];  // (1024,1024)
    const float* U      = (const float*)d_in[4];  // (1024,1024)
    const float* v      = (const float*)d_in[5];  // (1024,1)
    float* out = (float*)d_out;                   // (32,4096)

    const int SMEM = 4 * STG_B + 128 * 4;  // 197120 B
    static int configured = 0;
    if (!configured) {
        cudaFuncSetAttribute(fused_gemm_fp16, cudaFuncAttributeMaxDynamicSharedMemorySize, SMEM);
        configured = 1;
    }

    convA_kernel<<<131072, 256>>>(matrix);
    packU_kernel<<<256, 256>>>(U);
    projv_kernel<<<dim3(DD / 64, BB), 256>>>(vec, W);
    fused_gemm_fp16<<<dim3(RR / 128, BB), 256, SMEM>>>(v);
    softmax_kernel<<<BB, 256>>>(mask, out);
}

// round 14
// speedup vs baseline: 1.7298x; 1.0539x over previous
#include <cuda_runtime.h>
#include <cuda_fp16.h>
#include <cstdint>

#define DD 1024
#define RR 4096
#define BB 32
#define NEG_INF_F (-1e9f)

// Scratch (no runtime device allocation allowed; static __device__ arrays OK)
__device__ float g_projv[BB * DD];
__device__ float g_scores[BB * RR];
__device__ __half g_Ah[(size_t)BB * RR * DD];   // 256MB: matrix pre-converted to fp16
// U fp16, packed per (k16-group, n): halves in order {0,1,8,9,2,3,10,11,4,5,12,13,6,7,14,15}
__device__ __half g_Uh2[DD * DD];

// ---------------------------------------------------------------------------
// helpers
// ---------------------------------------------------------------------------
__device__ __forceinline__ float fast_tanh(float x) {
    float y;
    asm("tanh.approx.f32 %0, %1;" : "=f"(y) : "f"(x));
    return y;
}

__device__ __forceinline__ void mma_fp16(float c[4], const uint32_t a[4], const uint32_t b[2]) {
    asm volatile(
        "mma.sync.aligned.m16n8k16.row.col.f32.f16.f16.f32 "
        "{%0,%1,%2,%3}, {%4,%5,%6,%7}, {%8,%9}, {%0,%1,%2,%3};\n"
        : "+f"(c[0]), "+f"(c[1]), "+f"(c[2]), "+f"(c[3])
        : "r"(a[0]), "r"(a[1]), "r"(a[2]), "r"(a[3]), "r"(b[0]), "r"(b[1]));
}

__device__ __forceinline__ void cp_async16(uint32_t sdst, const void* gsrc) {
    asm volatile("cp.async.cg.shared.global [%0], [%1], 16;\n" :: "r"(sdst), "l"(gsrc));
}

// ldmatrix x4 (b16): four 8x8 fp16 tiles == one m16n8k16 A fragment
__device__ __forceinline__ void ldsm_x4(uint32_t r[4], uint32_t saddr) {
    asm volatile("ldmatrix.sync.aligned.m8n8.x4.shared.b16 {%0,%1,%2,%3}, [%4];\n"
                 : "=r"(r[0]), "=r"(r[1]), "=r"(r[2]), "=r"(r[3]) : "r"(saddr));
}

// ---------------------------------------------------------------------------
// Kernel 0a: convert matrix fp32 -> fp16 (RN). One float4 per thread.
// ---------------------------------------------------------------------------
__global__ void convA_kernel(const float* __restrict__ M) {
    const size_t idx = (size_t)blockIdx.x * 256 + threadIdx.x;  // float4 index
    const float4 v = ((const float4*)M)[idx];
    __half2 h0 = __floats2half2_rn(v.x, v.y);
    __half2 h1 = __floats2half2_rn(v.z, v.w);
    uint2 o;
    o.x = *(uint32_t*)&h0;
    o.y = *(uint32_t*)&h1;
    ((uint2*)g_Ah)[idx] = o;
}

// ---------------------------------------------------------------------------
// Kernel 0b: pack U fp32 -> fp16 [k16-group][n][16] with fragment-order k.
// ---------------------------------------------------------------------------
__global__ void packU_kernel(const float* __restrict__ U) {
    const int id = blockIdx.x * 256 + threadIdx.x;   // 0..65535
    const int kg = id >> 10;
    const int n = id & 1023;
    const int ord[16] = {0, 1, 8, 9, 2, 3, 10, 11, 4, 5, 12, 13, 6, 7, 14, 15};
    __half h[16];
#pragma unroll
    for (int i = 0; i < 16; ++i)
        h[i] = __float2half_rn(U[(size_t)(kg * 16 + ord[i]) * DD + n]);
    uint4* dst = (uint4*)(g_Uh2 + (size_t)id * 16);
    dst[0] = *(uint4*)&h[0];
    dst[1] = *(uint4*)&h[8];
}

// ---------------------------------------------------------------------------
// Kernel 1: proj_v = vector @ W  (B x D) fp32, k-split x4 (R10 version, proven)
// ---------------------------------------------------------------------------
__global__ void projv_kernel(const float* __restrict__ vec, const float* __restrict__ W) {
    __shared__ float vs[DD];
    __shared__ float part[4][64];
    const int b = blockIdx.y;
    const int n0 = blockIdx.x * 64;
    const int n = threadIdx.x & 63;
    const int kp = threadIdx.x >> 6;

    for (int k = threadIdx.x; k < DD; k += 256) vs[k] = vec[b * DD + k];
    __syncthreads();

    const float* Wp = W + (size_t)(kp * 256) * DD + n0 + n;
    const float* vp = vs + kp * 256;
    float acc = 0.0f;
#pragma unroll 8
    for (int k = 0; k < 256; ++k) acc = fmaf(vp[k], Wp[(size_t)k * DD], acc);
    part[kp][n] = acc;
    __syncthreads();
    if (kp == 0)
        g_projv[b * DD + n0 + n] = part[0][n] + part[1][n] + part[2][n] + part[3][n];
}

// ---------------------------------------------------------------------------
// Kernel 2: fused proj_m GEMM (fp16 m16n8k16) + tanh(+proj_v).v
// TWO CTAs PER SM: 128 threads, 4 warps (2M x 2N), warp tile 64x64.
// CTA tile 128(M) x 128(N-pass, x8), K-chunk 64 (x16/pass), 2-stage double
// buffer, one __syncthreads per chunk: wait -> sync -> issue(s+1) -> compute(s).
// Stage: A 128x64 fp16 XOR-swizzled (16KB) + B [4 k16][128 n][32B] (16KB) = 32KB.
// 2 stages + 128 score floats = 66048 B/CTA -> 2 CTAs co-resident.
// ---------------------------------------------------------------------------
#define STG_B  32768u
#define B_OFFB 16384u
#define NTOT   128           // 8 N-passes x 16 K64-chunks

__global__ __launch_bounds__(128, 2)
void fused_gemm_fp16(const float* __restrict__ vvec) {
    extern __shared__ __align__(128) float smem[];
    float* s_score = (float*)((char*)smem + 2 * STG_B);

    const int tid = threadIdx.x;
    const int warp = tid >> 5;
    const int lane = tid & 31;
    const int wm = warp & 1;       // 0..1  (64 rows each)
    const int wn = warp >> 1;      // 0..1  (64 cols each)
    const int g = lane >> 2;       // 0..7
    const int t = lane & 3;        // 0..3

    const int b = blockIdx.y;
    const int row0 = blockIdx.x * 128;

    s_score[tid] = 0.0f;

    const __half* Ag = g_Ah + ((size_t)b * RR + row0) * DD;
    const uint32_t sb = (uint32_t)__cvta_generic_to_shared(smem);

    // ldmatrix lane roles
    const int r7 = lane & 7;
    const int mh = lane >> 4;                      // col 16B-half (k +8)
    const int mrow = ((lane >> 3) & 1) * 8 + r7;   // row-in-16-tile

    // A cp.async mapping: rows ar+16i (i<8), 16B chunk ac (8 halves)
    const int ar = tid >> 3, ac = tid & 7;         // ar 0..15
    const uint32_t a_sw = (uint32_t)(ar & 7);      // row&7 invariant under +16

    auto issue_loads = [&](int sl) {
        const uint32_t slot = (uint32_t)(sl & 1);
        const int kt = sl & 15;
        const int n0 = (sl >> 4) * 128;
        const uint32_t abase = sb + slot * STG_B;
        const uint32_t bbase = abase + B_OFFB;
        const __half* asrc = Ag + (size_t)ar * DD + kt * 64 + ac * 8;
#pragma unroll
        for (int i = 0; i < 8; ++i) {
            const int row = ar + i * 16;
            cp_async16(abase + (uint32_t)(row * 128) + ((((uint32_t)ac) ^ a_sw) << 4),
                       asrc + (size_t)i * 16 * DD);
        }
        // B: 1024 16B-chunks; chunk c: kg_l=c>>8, n=(c>>1)&127, half=c&1
#pragma unroll
        for (int i = 0; i < 8; ++i) {
            const int c = i * 128 + tid;
            const int kg_l = c >> 8;
            const int n = (c >> 1) & 127;
            const int half = c & 1;
            cp_async16(bbase + (uint32_t)c * 16u,
                       g_Uh2 + ((size_t)(kt * 4 + kg_l) * DD + n0 + n) * 16 + half * 8);
        }
    };

    // prefetch chunk 0 into slot 0
    issue_loads(0);
    asm volatile("cp.async.commit_group;\n");

    float acc[4][8][4];
#pragma unroll
    for (int i = 0; i < 4; ++i)
#pragma unroll
        for (int j = 0; j < 8; ++j)
#pragma unroll
            for (int q = 0; q < 4; ++q) acc[i][j][q] = 0.0f;

    const float* pv = g_projv + b * DD;

    for (int s = 0; s < NTOT; ++s) {
        asm volatile("cp.async.wait_group 0;\n");   // chunk s resident
        __syncthreads();                            // slot (s+1)&1 readers done

        if (s + 1 < NTOT) {                         // issue chunk s+1
            issue_loads(s + 1);
            asm volatile("cp.async.commit_group;\n");
        }

        const uint32_t slot = (uint32_t)(s & 1);
        const uint32_t Ab32 = sb + slot * STG_B;
        const __half* Bh = (const __half*)((const char*)smem + slot * STG_B + B_OFFB);

        uint32_t afr[2][4][4];
        uint32_t bfr[2][8][2];
        auto load_frags = [&](int ks, int buf) {
            const uint32_t cx = (uint32_t)((2 * ks + mh) ^ r7) << 4;
#pragma unroll
            for (int i = 0; i < 4; ++i) {
                const int row = wm * 64 + i * 16 + mrow;
                ldsm_x4(afr[buf][i], Ab32 + (uint32_t)(row * 128) + cx);
            }
            const __half* bks = Bh + ks * 2048 + t * 4;  // ks*(128 cols * 16h)
#pragma unroll
            for (int j = 0; j < 8; ++j) {
                const uint2 p = *(const uint2*)(bks + (wn * 64 + j * 8 + g) * 16);
                bfr[buf][j][0] = p.x;   // k = 2t, 2t+1
                bfr[buf][j][1] = p.y;   // k = 2t+8, 2t+9
            }
        };

        load_frags(0, 0);
#pragma unroll
        for (int ks = 0; ks < 4; ++ks) {
            const int cur = ks & 1;
            if (ks < 3) load_frags(ks + 1, cur ^ 1);
#pragma unroll
            for (int i = 0; i < 4; ++i)
#pragma unroll
                for (int j = 0; j < 8; ++j)
                    mma_fp16(acc[i][j], afr[cur][i], bfr[cur][j]);
        }

        if ((s & 15) == 15) {
            // epilogue for this 128-col pass: tanh(acc + pv) . v
            const int n0 = (s >> 4) * 128;
            float ps[4][2];
#pragma unroll
            for (int i = 0; i < 4; ++i) { ps[i][0] = 0.0f; ps[i][1] = 0.0f; }
#pragma unroll
            for (int j = 0; j < 8; ++j) {
                const int cb = n0 + wn * 64 + j * 8 + 2 * t;
                const float2 pvv = *(const float2*)(pv + cb);
                const float2 vv = *(const float2*)(vvec + cb);
#pragma unroll
                for (int i = 0; i < 4; ++i) {
                    ps[i][0] = fmaf(fast_tanh(acc[i][j][0] + pvv.x), vv.x, ps[i][0]);
                    ps[i][0] = fmaf(fast_tanh(acc[i][j][1] + pvv.y), vv.y, ps[i][0]);
                    ps[i][1] = fmaf(fast_tanh(acc[i][j][2] + pvv.x), vv.x, ps[i][1]);
                    ps[i][1] = fmaf(fast_tanh(acc[i][j][3] + pvv.y), vv.y, ps[i][1]);
                    acc[i][j][0] = 0.0f; acc[i][j][1] = 0.0f;
                    acc[i][j][2] = 0.0f; acc[i][j][3] = 0.0f;
                }
            }
#pragma unroll
            for (int i = 0; i < 4; ++i)
#pragma unroll
                for (int h = 0; h < 2; ++h) {
                    float x = ps[i][h];
                    x += __shfl_xor_sync(0xffffffffu, x, 1);
                    x += __shfl_xor_sync(0xffffffffu, x, 2);
                    if (t == 0) atomicAdd(&s_score[wm * 64 + i * 16 + h * 8 + g], x);
                }
        }
    }

    __syncthreads();
    g_scores[(size_t)b * RR + row0 + tid] = s_score[tid];
}

// ---------------------------------------------------------------------------
// Kernel 3: masked softmax over R per batch. grid (B), 256 threads.
// ---------------------------------------------------------------------------
__global__ void softmax_kernel(const int* __restrict__ mask, float* __restrict__ out) {
    const int b = blockIdx.x;
    __shared__ float red[256];
    const float* s = g_scores + (size_t)b * RR;
    const int* m = mask + (size_t)b * RR;

    float l[16];
    float lmax = -3.0e38f;
#pragma unroll
    for (int i = 0; i < 16; ++i) {
        const int r = threadIdx.x + i * 256;
        l[i] = (m[r] > 0) ? s[r] : NEG_INF_F;
        lmax = fmaxf(lmax, l[i]);
    }
    red[threadIdx.x] = lmax;
    __syncthreads();
    for (int off = 128; off > 0; off >>= 1) {
        if (threadIdx.x < off) red[threadIdx.x] = fmaxf(red[threadIdx.x], red[threadIdx.x + off]);
        __syncthreads();
    }
    const float gmax = red[0];
    __syncthreads();

    float e[16];
    float lsum = 0.0f;
#pragma unroll
    for (int i = 0; i < 16; ++i) {
        e[i] = __expf(l[i] - gmax);
        lsum += e[i];
    }
    red[threadIdx.x] = lsum;
    __syncthreads();
    for (int off = 128; off > 0; off >>= 1) {
        if (threadIdx.x < off) red[threadIdx.x] += red[threadIdx.x + off];
        __syncthreads();
    }
    const float inv = __frcp_rn(red[0]);
#pragma unroll
    for (int i = 0; i < 16; ++i)
        out[(size_t)b * RR + threadIdx.x + i * 256] = e[i] * inv;
}

// ---------------------------------------------------------------------------
// launch
// ---------------------------------------------------------------------------
extern "C" void kernel_launch(void* const* d_in, const int* in_sizes, int n_in,
                              void* d_out, int out_size) {
    (void)in_sizes; (void)n_in; (void)out_size;
    const float* vec    = (const float*)d_in[0];  // (32,1024)
    const float* matrix = (const float*)d_in[1];  // (32,4096,1024)
    const int*   mask   = (const int*)  d_in[2];  // (32,4096)
    const float* W      = (const float*)d_in[3];  // (1024,1024)
    const float* U      = (const float*)d_in[4];  // (1024,1024)
    const float* v      = (const float*)d_in[5];  // (1024,1)
    float* out = (float*)d_out;                   // (32,4096)

    const int SMEM = 2 * STG_B + 128 * 4;  // 66048 B
    static int configured = 0;
    if (!configured) {
        cudaFuncSetAttribute(fused_gemm_fp16, cudaFuncAttributeMaxDynamicSharedMemorySize, SMEM);
        configured = 1;
    }

    convA_kernel<<<131072, 256>>>(matrix);
    packU_kernel<<<256, 256>>>(U);
    projv_kernel<<<dim3(DD / 64, BB), 256>>>(vec, W);
    fused_gemm_fp16<<<dim3(RR / 128, BB), 128, SMEM>>>(v);
    softmax_kernel<<<BB, 256>>>(mask, out);
}